// round 3
// baseline (speedup 1.0000x reference)
#include <cuda_runtime.h>

#define NN 8192
#define MM 2048
#define DD 256
#define DHH 8
#define ROW_CAP 64
#define COL_CAP 128
#define PROJ_BLOCKS 40          // (NN+MM)/256
#define SCAN_BLOCKS 2048
#define SCAN_ITERS 8            // NN*MM/4 / (SCAN_BLOCKS*256)
#define RBLK 148                // persistent kernel: one block per SM, single wave
#define RTHREADS 256
#define NWARP (RBLK * (RTHREADS / 32))

// ---------------- scratch (static device globals; zero-init at load) ---------
__device__ float g_WX[NN * DHH];
__device__ float g_sx[NN];   // WX @ alpha_x[:dh]
__device__ float g_s2[NN];   // WX @ alpha_e[dh:]
__device__ float g_se[MM];   // WE @ alpha_x[dh:]
__device__ float g_s1[MM];   // WE @ alpha_e[:dh]
__device__ int   g_row_cnt[NN];        // must be 0 at kernel_launch entry
__device__ int   g_col_cnt[MM];        // (zero at load; re-zeroed in k_rest tail)
__device__ int   g_row_edges[NN * ROW_CAP];
__device__ int   g_col_nodes[MM * COL_CAP];
__device__ float g_row_sum[NN];
__device__ float g_col_sum[MM];
__device__ float g_Enew[MM * DHH];
__device__ float g_empty_wx[DHH];      // must be 0 at entry (same invariant)
__device__ float g_empty_en[DHH];

// software grid barrier state (gen monotonically increases across replays; ok)
__device__ int          g_bar_count;
__device__ volatile int g_bar_gen;

__device__ __forceinline__ float leaky(float x) { return x >= 0.f ? x : 0.2f * x; }
__device__ __forceinline__ float elu(float x)   { return x > 0.f ? x : expm1f(x); }

__device__ __forceinline__ void grid_bar() {
    __threadfence();
    __syncthreads();
    if (threadIdx.x == 0) {
        int g = g_bar_gen;
        if (atomicAdd(&g_bar_count, 1) == RBLK - 1) {
            g_bar_count = 0;
            __threadfence();
            g_bar_gen = g + 1;
        } else {
            while (g_bar_gen == g) { }
        }
    }
    __syncthreads();
    __threadfence();
}

// ---------------- K1: fused projection + H scan (independent block groups) ---
__global__ void k_main(const float* __restrict__ X, const float* __restrict__ E,
                       const float* __restrict__ H, const float* __restrict__ W,
                       const float* __restrict__ ax, const float* __restrict__ ae) {
    if (blockIdx.x >= PROJ_BLOCKS) {
        // ---- scan portion: fully unrolled, MLP=8 ----
        int t = (blockIdx.x - PROJ_BLOCKS) * blockDim.x + threadIdx.x;
        const int stride = SCAN_BLOCKS * 256;
        const uint4* H4 = reinterpret_cast<const uint4*>(H);
        uint4 v[SCAN_ITERS];
#pragma unroll
        for (int it = 0; it < SCAN_ITERS; it++) v[it] = H4[t + it * stride];
#pragma unroll
        for (int it = 0; it < SCAN_ITERS; it++) {
            uint4 h = v[it];
            if (h.x | h.y | h.z | h.w) {
                int base = (t + it * stride) * 4;
                unsigned c4[4] = {h.x, h.y, h.z, h.w};
#pragma unroll
                for (int c = 0; c < 4; c++) {
                    if (c4[c]) {
                        int lin = base + c;
                        int i = lin >> 11;        // / MM
                        int k = lin & (MM - 1);   // % MM
                        int p = atomicAdd(&g_row_cnt[i], 1);
                        if (p < ROW_CAP) g_row_edges[i * ROW_CAP + p] = k;
                        int q = atomicAdd(&g_col_cnt[k], 1);
                        if (q < COL_CAP) g_col_nodes[k * COL_CAP + q] = i;
                    }
                }
            }
        }
        return;
    }

    // ---- projection portion: rows 0..NN-1 -> X, NN..NN+MM-1 -> E ----
    __shared__ float sW[DD * DHH];
    __shared__ float sax[2 * DHH], sae[2 * DHH];
    for (int j = threadIdx.x; j < DD * DHH; j += blockDim.x) sW[j] = W[j];
    if (threadIdx.x < 2 * DHH) {
        sax[threadIdx.x] = ax[threadIdx.x];
        sae[threadIdx.x] = ae[threadIdx.x];
    }
    __syncthreads();

    int r = blockIdx.x * blockDim.x + threadIdx.x;   // 0..10239
    const float* src = (r < NN) ? (X + (size_t)r * DD)
                                : (E + (size_t)(r - NN) * DD);
    float acc[DHH];
#pragma unroll
    for (int d = 0; d < DHH; d++) acc[d] = 0.f;

    const float4* Ar = reinterpret_cast<const float4*>(src);
#pragma unroll 4
    for (int j4 = 0; j4 < DD / 4; j4++) {
        float4 x = Ar[j4];
        int j = 4 * j4;
#pragma unroll
        for (int d = 0; d < DHH; d++) acc[d] += x.x * sW[(j + 0) * DHH + d];
#pragma unroll
        for (int d = 0; d < DHH; d++) acc[d] += x.y * sW[(j + 1) * DHH + d];
#pragma unroll
        for (int d = 0; d < DHH; d++) acc[d] += x.z * sW[(j + 2) * DHH + d];
#pragma unroll
        for (int d = 0; d < DHH; d++) acc[d] += x.w * sW[(j + 3) * DHH + d];
    }

    if (r < NN) {
        float d1 = 0.f, d2 = 0.f;
#pragma unroll
        for (int d = 0; d < DHH; d++) {
            d1 += acc[d] * sax[d];          // alpha_x[:dh]
            d2 += acc[d] * sae[DHH + d];    // alpha_e[dh:]
            g_WX[r * DHH + d] = acc[d];
        }
        g_sx[r] = d1; g_s2[r] = d2;
    } else {
        int k = r - NN;
        float d1 = 0.f, d2 = 0.f;
#pragma unroll
        for (int d = 0; d < DHH; d++) {
            d1 += acc[d] * sax[DHH + d];    // alpha_x[dh:]
            d2 += acc[d] * sae[d];          // alpha_e[:dh]
        }
        g_se[k] = d1; g_s1[k] = d2;
    }
}

// ---------------- K2: persistent kernel: stats -> E_new -> X_new -> cleanup --
__global__ void __launch_bounds__(RTHREADS) k_rest(float* __restrict__ out) {
    const int t = blockIdx.x * RTHREADS + threadIdx.x;   // 0..37887
    const float invM = 1.f / MM;
    const float invN = 1.f / NN;

    // ---- phase A: per-node exp-sum (no max; logits are small), empty_wx,
    //               and per-edge exp-sum ----
    if (t < NN) {
        int i = t;
        int cnt = min(g_row_cnt[i], ROW_CAP);
        if (cnt == 0) {
#pragma unroll
            for (int d = 0; d < DHH; d++) atomicAdd(&g_empty_wx[d], g_WX[i * DHH + d]);
        } else {
            float sxi = g_sx[i];
            float s = 0.f;
            for (int j = 0; j < cnt; j++) {
                int k = g_row_edges[i * ROW_CAP + j];
                s += __expf(leaky(sxi + g_se[k]));
            }
            g_row_sum[i] = s;
        }
    }
    if (t < MM) {
        int k = t;
        int cnt = min(g_col_cnt[k], COL_CAP);
        if (cnt > 0) {
            float s1k = g_s1[k];
            float s = 0.f;
            for (int j = 0; j < cnt; j++) {
                int i = g_col_nodes[k * COL_CAP + j];
                s += __expf(leaky(s1k + g_s2[i]));
            }
            g_col_sum[k] = s;
        }
    }
    grid_bar();

    // ---- phase B: E_new, warp per edge ----
    {
        int w = t >> 5;
        int lane = t & 31;
        for (int k = w; k < MM; k += NWARP) {
            int cnt = min(g_col_cnt[k], COL_CAP);
            if (cnt == 0) {
                if (lane < DHH) {
                    float o = elu(invM * g_empty_wx[lane]);
                    atomicAdd(&g_empty_en[lane], o);
                }
                continue;
            }
            float sek = g_se[k];
            float acc[DHH];
#pragma unroll
            for (int d = 0; d < DHH; d++) acc[d] = 0.f;
            for (int j = lane; j < cnt; j += 32) {
                int i = g_col_nodes[k * COL_CAP + j];
                float wt = __expf(leaky(g_sx[i] + sek)) / g_row_sum[i];
                const float4* wx = reinterpret_cast<const float4*>(&g_WX[i * DHH]);
                float4 a = wx[0], b = wx[1];
                acc[0] += wt * a.x; acc[1] += wt * a.y; acc[2] += wt * a.z; acc[3] += wt * a.w;
                acc[4] += wt * b.x; acc[5] += wt * b.y; acc[6] += wt * b.z; acc[7] += wt * b.w;
            }
#pragma unroll
            for (int d = 0; d < DHH; d++)
#pragma unroll
                for (int off = 16; off > 0; off >>= 1)
                    acc[d] += __shfl_xor_sync(0xffffffffu, acc[d], off);
            if (lane == 0) {
#pragma unroll
                for (int d = 0; d < DHH; d++)
                    g_Enew[k * DHH + d] = elu(acc[d] + invM * g_empty_wx[d]);
            }
        }
    }
    grid_bar();

    // ---- phase C: X_new, thread per node ----
    if (t < NN) {
        int i = t;
        int cnt = min(g_row_cnt[i], ROW_CAP);
        float s2i = g_s2[i];
        float acc[DHH];
#pragma unroll
        for (int d = 0; d < DHH; d++) acc[d] = 0.f;
        for (int j = 0; j < cnt; j++) {
            int k = g_row_edges[i * ROW_CAP + j];
            float wt = __expf(leaky(g_s1[k] + s2i)) / g_col_sum[k];
            const float4* en = reinterpret_cast<const float4*>(&g_Enew[k * DHH]);
            float4 a = en[0], b = en[1];
            acc[0] += wt * a.x; acc[1] += wt * a.y; acc[2] += wt * a.z; acc[3] += wt * a.w;
            acc[4] += wt * b.x; acc[5] += wt * b.y; acc[6] += wt * b.z; acc[7] += wt * b.w;
        }
#pragma unroll
        for (int d = 0; d < DHH; d++)
            out[i * DHH + d] = elu(acc[d] + invN * g_empty_en[d]);
    }
    grid_bar();   // all reads of counters/empties done before cleanup

    // ---- cleanup: restore zero-invariant for the next graph replay ----
    if (t < NN) g_row_cnt[t] = 0;
    if (t < MM) g_col_cnt[t] = 0;
    if (t < DHH) { g_empty_wx[t] = 0.f; g_empty_en[t] = 0.f; }
}

// -----------------------------------------------------------------------------
extern "C" void kernel_launch(void* const* d_in, const int* in_sizes, int n_in,
                              void* d_out, int out_size) {
    const float* X  = (const float*)d_in[0];
    const float* E  = (const float*)d_in[1];
    const float* H  = (const float*)d_in[2];
    const float* W  = (const float*)d_in[3];
    const float* ax = (const float*)d_in[4];
    const float* ae = (const float*)d_in[5];
    float* out = (float*)d_out;

    k_main<<<PROJ_BLOCKS + SCAN_BLOCKS, 256>>>(X, E, H, W, ax, ae);
    k_rest<<<RBLK, RTHREADS>>>(out);
}

// round 4
// speedup vs baseline: 1.4005x; 1.4005x over previous
#include <cuda_runtime.h>

#define NN 8192
#define MM 2048
#define DD 256
#define DHH 8
#define ROW_CAP 64
#define COL_CAP 128
#define PROJ_BLOCKS 40          // (NN+MM)/256
#define SCAN_BLOCKS 2048
#define SCAN_ITERS 8            // NN*MM/4 / (SCAN_BLOCKS*256)

// ---------------- scratch (static device globals; zero-init at load) ---------
__device__ __align__(16) float g_WX[NN * DHH];
__device__ float g_sx[NN];   // WX @ alpha_x[:dh]
__device__ float g_s2[NN];   // WX @ alpha_e[dh:]
__device__ float g_se[MM];   // WE @ alpha_x[dh:]
__device__ float g_s1[MM];   // WE @ alpha_e[:dh]
__device__ int   g_row_cnt[NN];        // zero at entry (load-zeroed; re-zeroed in k_xnew)
__device__ int   g_col_cnt[MM];
__device__ __align__(16) int g_row_edges[NN * ROW_CAP];
__device__ int   g_col_nodes[MM * COL_CAP];
// packed per-node record: [sx, 1/rowSum, s2, 0, WX0..3, WX4..7]  (stride 16 floats)
__device__ __align__(16) float g_npack[NN * 16];
// packed per-edge record: [s1, 1/colSum, 0, 0, Enew0..3, Enew4..7]
__device__ __align__(16) float g_epack[MM * 16];
__device__ __align__(16) float g_empty_wx[DHH];   // zeroed by k_main each replay
__device__ __align__(16) float g_empty_en[DHH];

__device__ __forceinline__ float leaky(float x) { return x >= 0.f ? x : 0.2f * x; }
__device__ __forceinline__ float elu(float x)   { return x > 0.f ? x : expm1f(x); }
__device__ __forceinline__ void pdl_wait()    { asm volatile("griddepcontrol.wait;" ::: "memory"); }
__device__ __forceinline__ void pdl_trigger() { asm volatile("griddepcontrol.launch_dependents;" ::: "memory"); }

// ---------------- K1: fused projection + H scan (independent block groups) ---
__global__ void k_main(const float* __restrict__ X, const float* __restrict__ E,
                       const float* __restrict__ H, const float* __restrict__ W,
                       const float* __restrict__ ax, const float* __restrict__ ae) {
    pdl_wait();   // previous replay's k_xnew must have finished (counters re-zeroed)
    if (blockIdx.x >= PROJ_BLOCKS) {
        // ---- scan portion: fully unrolled, MLP=8 ----
        int t = (blockIdx.x - PROJ_BLOCKS) * blockDim.x + threadIdx.x;
        const int stride = SCAN_BLOCKS * 256;
        const uint4* H4 = reinterpret_cast<const uint4*>(H);
        uint4 v[SCAN_ITERS];
#pragma unroll
        for (int it = 0; it < SCAN_ITERS; it++) v[it] = H4[t + it * stride];
#pragma unroll
        for (int it = 0; it < SCAN_ITERS; it++) {
            uint4 h = v[it];
            if (h.x | h.y | h.z | h.w) {
                int base = (t + it * stride) * 4;
                unsigned c4[4] = {h.x, h.y, h.z, h.w};
#pragma unroll
                for (int c = 0; c < 4; c++) {
                    if (c4[c]) {
                        int lin = base + c;
                        int i = lin >> 11;        // / MM
                        int k = lin & (MM - 1);   // % MM
                        int p = atomicAdd(&g_row_cnt[i], 1);
                        if (p < ROW_CAP) g_row_edges[i * ROW_CAP + p] = k;
                        int q = atomicAdd(&g_col_cnt[k], 1);
                        if (q < COL_CAP) g_col_nodes[k * COL_CAP + q] = i;
                    }
                }
            }
        }
        pdl_trigger();
        return;
    }

    // ---- projection portion: rows 0..NN-1 -> X, NN..NN+MM-1 -> E ----
    __shared__ float sW[DD * DHH];
    __shared__ float sax[2 * DHH], sae[2 * DHH];
    for (int j = threadIdx.x; j < DD * DHH; j += blockDim.x) sW[j] = W[j];
    if (threadIdx.x < 2 * DHH) {
        sax[threadIdx.x] = ax[threadIdx.x];
        sae[threadIdx.x] = ae[threadIdx.x];
    }
    __syncthreads();

    int r = blockIdx.x * blockDim.x + threadIdx.x;   // 0..10239
    if (r < DHH) { g_empty_wx[r] = 0.f; g_empty_en[r] = 0.f; }

    const float* src = (r < NN) ? (X + (size_t)r * DD)
                                : (E + (size_t)(r - NN) * DD);
    float acc[DHH];
#pragma unroll
    for (int d = 0; d < DHH; d++) acc[d] = 0.f;

    const float4* Ar = reinterpret_cast<const float4*>(src);
#pragma unroll 4
    for (int j4 = 0; j4 < DD / 4; j4++) {
        float4 x = Ar[j4];
        int j = 4 * j4;
#pragma unroll
        for (int d = 0; d < DHH; d++) acc[d] += x.x * sW[(j + 0) * DHH + d];
#pragma unroll
        for (int d = 0; d < DHH; d++) acc[d] += x.y * sW[(j + 1) * DHH + d];
#pragma unroll
        for (int d = 0; d < DHH; d++) acc[d] += x.z * sW[(j + 2) * DHH + d];
#pragma unroll
        for (int d = 0; d < DHH; d++) acc[d] += x.w * sW[(j + 3) * DHH + d];
    }

    if (r < NN) {
        float d1 = 0.f, d2 = 0.f;
#pragma unroll
        for (int d = 0; d < DHH; d++) {
            d1 += acc[d] * sax[d];          // alpha_x[:dh]
            d2 += acc[d] * sae[DHH + d];    // alpha_e[dh:]
            g_WX[r * DHH + d] = acc[d];
        }
        g_sx[r] = d1; g_s2[r] = d2;
    } else {
        int k = r - NN;
        float d1 = 0.f, d2 = 0.f;
#pragma unroll
        for (int d = 0; d < DHH; d++) {
            d1 += acc[d] * sax[DHH + d];    // alpha_x[dh:]
            d2 += acc[d] * sae[d];          // alpha_e[:dh]
        }
        g_se[k] = d1; g_s1[k] = d2;
    }
    pdl_trigger();
}

// ---------------- K2: per-node exp-sum -> npack; empty-node sum --------------
__global__ void k_nodestats() {
    pdl_wait();
    int i = blockIdx.x * blockDim.x + threadIdx.x;   // exactly NN threads
    int cnt = min(g_row_cnt[i], ROW_CAP);
    float4 w0 = *reinterpret_cast<const float4*>(&g_WX[i * DHH]);
    float4 w1 = *reinterpret_cast<const float4*>(&g_WX[i * DHH + 4]);
    if (cnt == 0) {
        atomicAdd(&g_empty_wx[0], w0.x); atomicAdd(&g_empty_wx[1], w0.y);
        atomicAdd(&g_empty_wx[2], w0.z); atomicAdd(&g_empty_wx[3], w0.w);
        atomicAdd(&g_empty_wx[4], w1.x); atomicAdd(&g_empty_wx[5], w1.y);
        atomicAdd(&g_empty_wx[6], w1.z); atomicAdd(&g_empty_wx[7], w1.w);
        pdl_trigger();
        return;
    }
    float sxi = g_sx[i], s2i = g_s2[i];
    float s = 0.f;
    const int4* idx4 = reinterpret_cast<const int4*>(&g_row_edges[i * ROW_CAP]);
    int nb = (cnt + 7) >> 3;
    for (int b = 0; b < nb; b++) {
        int4 a = idx4[2 * b], c = idx4[2 * b + 1];   // stale slots: still in [0,MM)
        int id[8] = {a.x, a.y, a.z, a.w, c.x, c.y, c.z, c.w};
        float v[8];
#pragma unroll
        for (int u = 0; u < 8; u++) v[u] = g_se[id[u]];
#pragma unroll
        for (int u = 0; u < 8; u++) {
            if (b * 8 + u < cnt) s += __expf(leaky(sxi + v[u]));
        }
    }
    float inv = 1.f / s;
    float4* np = reinterpret_cast<float4*>(&g_npack[i * 16]);
    np[0] = make_float4(sxi, inv, s2i, 0.f);
    np[1] = w0;
    np[2] = w1;
    pdl_trigger();
}

// ---------------- K3: E_new + col softmax -> epack; warp per edge ------------
__global__ void k_enew() {
    pdl_wait();
    int gid = blockIdx.x * blockDim.x + threadIdx.x;
    int k = gid >> 5;                                 // exactly MM warps
    int lane = gid & 31;
    int cnt = min(g_col_cnt[k], COL_CAP);
    const float invM = 1.f / MM;

    if (cnt == 0) {
        if (lane < DHH)
            atomicAdd(&g_empty_en[lane], elu(invM * g_empty_wx[lane]));
        pdl_trigger();
        return;
    }

    float sek = g_se[k], s1k = g_s1[k];
    float colS = 0.f;
    float acc[DHH];
#pragma unroll
    for (int d = 0; d < DHH; d++) acc[d] = 0.f;

    for (int j = lane; j < cnt; j += 32) {
        int i = g_col_nodes[k * COL_CAP + j];
        const float4* np = reinterpret_cast<const float4*>(&g_npack[i * 16]);
        float4 p0 = np[0], p1 = np[1], p2 = np[2];
        colS += __expf(leaky(s1k + p0.z));
        float wt = __expf(leaky(p0.x + sek)) * p0.y;
        acc[0] += wt * p1.x; acc[1] += wt * p1.y; acc[2] += wt * p1.z; acc[3] += wt * p1.w;
        acc[4] += wt * p2.x; acc[5] += wt * p2.y; acc[6] += wt * p2.z; acc[7] += wt * p2.w;
    }

#pragma unroll
    for (int off = 16; off > 0; off >>= 1)
        colS += __shfl_xor_sync(0xffffffffu, colS, off);
#pragma unroll
    for (int d = 0; d < DHH; d++)
#pragma unroll
        for (int off = 16; off > 0; off >>= 1)
            acc[d] += __shfl_xor_sync(0xffffffffu, acc[d], off);

    if (lane == 0) {
        float4 ew0 = *reinterpret_cast<const float4*>(&g_empty_wx[0]);
        float4 ew1 = *reinterpret_cast<const float4*>(&g_empty_wx[4]);
        float4* ep = reinterpret_cast<float4*>(&g_epack[k * 16]);
        ep[0] = make_float4(s1k, 1.f / colS, 0.f, 0.f);
        ep[1] = make_float4(elu(acc[0] + invM * ew0.x), elu(acc[1] + invM * ew0.y),
                            elu(acc[2] + invM * ew0.z), elu(acc[3] + invM * ew0.w));
        ep[2] = make_float4(elu(acc[4] + invM * ew1.x), elu(acc[5] + invM * ew1.y),
                            elu(acc[6] + invM * ew1.z), elu(acc[7] + invM * ew1.w));
    }
    pdl_trigger();
}

// ---------------- K4: X_new + counter re-zero; thread per node ---------------
__global__ void k_xnew(float* __restrict__ out) {
    pdl_wait();
    int i = blockIdx.x * blockDim.x + threadIdx.x;   // exactly NN threads
    int cnt = min(g_row_cnt[i], ROW_CAP);
    float s2i = g_s2[i];
    float acc[DHH];
#pragma unroll
    for (int d = 0; d < DHH; d++) acc[d] = 0.f;

    const int4* idx4 = reinterpret_cast<const int4*>(&g_row_edges[i * ROW_CAP]);
    int nb = (cnt + 3) >> 2;
    for (int b = 0; b < nb; b++) {
        int4 a = idx4[b];
        int id[4] = {a.x, a.y, a.z, a.w};
#pragma unroll
        for (int u = 0; u < 4; u++) {
            if (b * 4 + u < cnt) {
                const float4* ep = reinterpret_cast<const float4*>(&g_epack[id[u] * 16]);
                float4 e0 = ep[0], e1 = ep[1], e2 = ep[2];
                float wt = __expf(leaky(e0.x + s2i)) * e0.y;
                acc[0] += wt * e1.x; acc[1] += wt * e1.y; acc[2] += wt * e1.z; acc[3] += wt * e1.w;
                acc[4] += wt * e2.x; acc[5] += wt * e2.y; acc[6] += wt * e2.z; acc[7] += wt * e2.w;
            }
        }
    }

    const float invN = 1.f / NN;
    float4 en0 = *reinterpret_cast<const float4*>(&g_empty_en[0]);
    float4 en1 = *reinterpret_cast<const float4*>(&g_empty_en[4]);
    float4 o0 = make_float4(elu(acc[0] + invN * en0.x), elu(acc[1] + invN * en0.y),
                            elu(acc[2] + invN * en0.z), elu(acc[3] + invN * en0.w));
    float4 o1 = make_float4(elu(acc[4] + invN * en1.x), elu(acc[5] + invN * en1.y),
                            elu(acc[6] + invN * en1.z), elu(acc[7] + invN * en1.w));
    reinterpret_cast<float4*>(out + (size_t)i * DHH)[0] = o0;
    reinterpret_cast<float4*>(out + (size_t)i * DHH)[1] = o1;

    // ---- restore zero-invariant for the next replay ----
    g_row_cnt[i] = 0;                  // own slot, already consumed above
    if (i < MM) g_col_cnt[i] = 0;      // no reader of col_cnt in this kernel
    pdl_trigger();
}

// -----------------------------------------------------------------------------
extern "C" void kernel_launch(void* const* d_in, const int* in_sizes, int n_in,
                              void* d_out, int out_size) {
    const float* X  = (const float*)d_in[0];
    const float* E  = (const float*)d_in[1];
    const float* H  = (const float*)d_in[2];
    const float* W  = (const float*)d_in[3];
    const float* ax = (const float*)d_in[4];
    const float* ae = (const float*)d_in[5];
    float* out = (float*)d_out;

    cudaLaunchAttribute attr;
    attr.id = cudaLaunchAttributeProgrammaticStreamSerialization;
    attr.val.programmaticStreamSerializationAllowed = 1;

    cudaLaunchConfig_t cfg = {};
    cfg.blockDim = dim3(256);
    cfg.dynamicSmemBytes = 0;
    cfg.stream = 0;
    cfg.attrs = &attr;
    cfg.numAttrs = 1;

    cfg.gridDim = dim3(PROJ_BLOCKS + SCAN_BLOCKS);
    cudaLaunchKernelEx(&cfg, k_main, X, E, H, W, ax, ae);

    cfg.gridDim = dim3(NN / 256);
    cudaLaunchKernelEx(&cfg, k_nodestats);

    cfg.gridDim = dim3(MM * 32 / 256);
    cudaLaunchKernelEx(&cfg, k_enew);

    cfg.gridDim = dim3(NN / 256);
    cudaLaunchKernelEx(&cfg, k_xnew, out);
}

// round 5
// speedup vs baseline: 1.4938x; 1.0667x over previous
#include <cuda_runtime.h>

#define NN 8192
#define MM 2048
#define DD 256
#define DHH 8
#define ROW_CAP 64
#define COL_CAP 128
#define PROJ_BLOCKS 40          // (NN+MM)/256
#define SCAN_BLOCKS 2048
#define SCAN_ITERS 8            // NN*MM/4 / (SCAN_BLOCKS*256)

// ---------------- scratch (static device globals; zero-init at load) ---------
__device__ __align__(16) float g_WX[NN * DHH];      // only used for proj->npack path
__device__ float g_sx[NN];
__device__ float g_s2[NN];
__device__ float g_se[MM];
__device__ float g_s1[MM];
__device__ int   g_row_cnt[NN];        // zero at entry; re-zeroed in k_xnew
__device__ int   g_col_cnt[MM];
__device__ __align__(16) int g_row_edges[NN * ROW_CAP];
__device__ int   g_col_nodes[MM * COL_CAP];
// packed per-node record: [sx, 1/rowSum, s2, 0, WX0..7, pad4]  (stride 16 floats)
__device__ __align__(16) float g_npack[NN * 16];
// packed per-edge record: [s1, 1/colSum, 0, 0, Enew0..7, pad4]
__device__ __align__(16) float g_epack[MM * 16];
__device__ __align__(16) float g_empty_wx[DHH];     // zeroed by k_main each replay
__device__ __align__(16) float g_empty_en[DHH];

__device__ __forceinline__ float leaky(float x) { return x >= 0.f ? x : 0.2f * x; }
__device__ __forceinline__ float elu(float x)   { return x > 0.f ? x : expm1f(x); }
__device__ __forceinline__ void pdl_wait()    { asm volatile("griddepcontrol.wait;" ::: "memory"); }
__device__ __forceinline__ void pdl_trigger() { asm volatile("griddepcontrol.launch_dependents;" ::: "memory"); }

// ---------------- K1: fused projection + H scan (independent block groups) ---
__global__ void k_main(const float* __restrict__ X, const float* __restrict__ E,
                       const float* __restrict__ H, const float* __restrict__ W,
                       const float* __restrict__ ax, const float* __restrict__ ae) {
    pdl_wait();   // previous replay's k_xnew re-zeroed counters
    if (blockIdx.x >= PROJ_BLOCKS) {
        int t = (blockIdx.x - PROJ_BLOCKS) * blockDim.x + threadIdx.x;
        const int stride = SCAN_BLOCKS * 256;
        const uint4* H4 = reinterpret_cast<const uint4*>(H);
        uint4 v[SCAN_ITERS];
#pragma unroll
        for (int it = 0; it < SCAN_ITERS; it++) v[it] = H4[t + it * stride];
#pragma unroll
        for (int it = 0; it < SCAN_ITERS; it++) {
            uint4 h = v[it];
            if (h.x | h.y | h.z | h.w) {
                int base = (t + it * stride) * 4;
                unsigned c4[4] = {h.x, h.y, h.z, h.w};
#pragma unroll
                for (int c = 0; c < 4; c++) {
                    if (c4[c]) {
                        int lin = base + c;
                        int i = lin >> 11;        // / MM
                        int k = lin & (MM - 1);   // % MM
                        int p = atomicAdd(&g_row_cnt[i], 1);
                        if (p < ROW_CAP) g_row_edges[i * ROW_CAP + p] = k;
                        int q = atomicAdd(&g_col_cnt[k], 1);
                        if (q < COL_CAP) g_col_nodes[k * COL_CAP + q] = i;
                    }
                }
            }
        }
        pdl_trigger();
        return;
    }

    // ---- projection: rows 0..NN-1 -> X, NN..NN+MM-1 -> E ----
    __shared__ float sW[DD * DHH];
    __shared__ float sax[2 * DHH], sae[2 * DHH];
    for (int j = threadIdx.x; j < DD * DHH; j += blockDim.x) sW[j] = W[j];
    if (threadIdx.x < 2 * DHH) {
        sax[threadIdx.x] = ax[threadIdx.x];
        sae[threadIdx.x] = ae[threadIdx.x];
    }
    __syncthreads();

    int r = blockIdx.x * blockDim.x + threadIdx.x;   // 0..10239
    if (r < DHH) { g_empty_wx[r] = 0.f; g_empty_en[r] = 0.f; }

    const float* src = (r < NN) ? (X + (size_t)r * DD)
                                : (E + (size_t)(r - NN) * DD);
    float acc[DHH];
#pragma unroll
    for (int d = 0; d < DHH; d++) acc[d] = 0.f;

    const float4* Ar = reinterpret_cast<const float4*>(src);
#pragma unroll 4
    for (int j4 = 0; j4 < DD / 4; j4++) {
        float4 x = Ar[j4];
        int j = 4 * j4;
#pragma unroll
        for (int d = 0; d < DHH; d++) acc[d] += x.x * sW[(j + 0) * DHH + d];
#pragma unroll
        for (int d = 0; d < DHH; d++) acc[d] += x.y * sW[(j + 1) * DHH + d];
#pragma unroll
        for (int d = 0; d < DHH; d++) acc[d] += x.z * sW[(j + 2) * DHH + d];
#pragma unroll
        for (int d = 0; d < DHH; d++) acc[d] += x.w * sW[(j + 3) * DHH + d];
    }

    if (r < NN) {
        float d1 = 0.f, d2 = 0.f;
#pragma unroll
        for (int d = 0; d < DHH; d++) {
            d1 += acc[d] * sax[d];          // alpha_x[:dh]
            d2 += acc[d] * sae[DHH + d];    // alpha_e[dh:]
        }
        g_sx[r] = d1; g_s2[r] = d2;
        // prebuild npack: p0=(sx, placeholder, s2, 0), p1/p2 = WX
        float4* np = reinterpret_cast<float4*>(&g_npack[r * 16]);
        np[0] = make_float4(d1, 0.f, d2, 0.f);
        np[1] = make_float4(acc[0], acc[1], acc[2], acc[3]);
        np[2] = make_float4(acc[4], acc[5], acc[6], acc[7]);
    } else {
        int k = r - NN;
        float d1 = 0.f, d2 = 0.f;
#pragma unroll
        for (int d = 0; d < DHH; d++) {
            d1 += acc[d] * sax[DHH + d];    // alpha_x[dh:]
            d2 += acc[d] * sae[d];          // alpha_e[:dh]
        }
        g_se[k] = d1; g_s1[k] = d2;
        g_epack[k * 16] = d2;               // epack p0.x = s1
    }
    pdl_trigger();
}

// ---------------- K2: per-node exp-sum (8 lanes/node) -> npack.inv -----------
__global__ void k_nodestats() {
    pdl_wait();
    int gid = blockIdx.x * blockDim.x + threadIdx.x;   // NN*8 threads
    int i = gid >> 3, l8 = gid & 7;
    int cnt = min(g_row_cnt[i], ROW_CAP);
    if (cnt == 0) {
        // lane d adds WX[i][d] (from npack) to empty_wx[d]
        atomicAdd(&g_empty_wx[l8], g_npack[i * 16 + 4 + l8]);
        pdl_trigger();
        return;
    }
    float sxi = g_sx[i];
    float s = 0.f;
    for (int j = l8; j < cnt; j += 8)
        s += __expf(leaky(sxi + g_se[g_row_edges[i * ROW_CAP + j]]));
    s += __shfl_xor_sync(0xffffffffu, s, 4);
    s += __shfl_xor_sync(0xffffffffu, s, 2);
    s += __shfl_xor_sync(0xffffffffu, s, 1);
    if (l8 == 0) g_npack[i * 16 + 1] = 1.f / s;
    pdl_trigger();
}

// ---------------- K3: E_new + col softmax; warp per edge ---------------------
__global__ void k_enew() {
    pdl_wait();
    int gid = blockIdx.x * blockDim.x + threadIdx.x;
    int k = gid >> 5;                                 // exactly MM warps
    int lane = gid & 31;
    int cnt = min(g_col_cnt[k], COL_CAP);
    const float invM = 1.f / MM;

    if (cnt == 0) {
        if (lane < DHH)
            atomicAdd(&g_empty_en[lane], elu(invM * g_empty_wx[lane]));
        pdl_trigger();
        return;
    }

    float sek = g_se[k], s1k = g_s1[k];
    float colS = 0.f;
    float acc[DHH];
#pragma unroll
    for (int d = 0; d < DHH; d++) acc[d] = 0.f;

    for (int j = lane; j < cnt; j += 32) {
        int i = g_col_nodes[k * COL_CAP + j];
        const float4* np = reinterpret_cast<const float4*>(&g_npack[i * 16]);
        float4 p0 = np[0], p1 = np[1], p2 = np[2];
        colS += __expf(leaky(s1k + p0.z));
        float wt = __expf(leaky(p0.x + sek)) * p0.y;
        acc[0] += wt * p1.x; acc[1] += wt * p1.y; acc[2] += wt * p1.z; acc[3] += wt * p1.w;
        acc[4] += wt * p2.x; acc[5] += wt * p2.y; acc[6] += wt * p2.z; acc[7] += wt * p2.w;
    }

#pragma unroll
    for (int off = 16; off > 0; off >>= 1)
        colS += __shfl_xor_sync(0xffffffffu, colS, off);
#pragma unroll
    for (int d = 0; d < DHH; d++)
#pragma unroll
        for (int off = 16; off > 0; off >>= 1)
            acc[d] += __shfl_xor_sync(0xffffffffu, acc[d], off);

    if (lane == 0) {
        float4 ew0 = *reinterpret_cast<const float4*>(&g_empty_wx[0]);
        float4 ew1 = *reinterpret_cast<const float4*>(&g_empty_wx[4]);
        g_epack[k * 16 + 1] = 1.f / colS;
        float4* ep = reinterpret_cast<float4*>(&g_epack[k * 16]);
        ep[1] = make_float4(elu(acc[0] + invM * ew0.x), elu(acc[1] + invM * ew0.y),
                            elu(acc[2] + invM * ew0.z), elu(acc[3] + invM * ew0.w));
        ep[2] = make_float4(elu(acc[4] + invM * ew1.x), elu(acc[5] + invM * ew1.y),
                            elu(acc[6] + invM * ew1.z), elu(acc[7] + invM * ew1.w));
    }
    pdl_trigger();
}

// ---------------- K4: X_new (8 lanes/node, dim-owning) + counter re-zero -----
__global__ void k_xnew(float* __restrict__ out) {
    pdl_wait();
    int gid = blockIdx.x * blockDim.x + threadIdx.x;   // NN*8 threads
    int i = gid >> 3, u = gid & 7;
    int cnt = min(g_row_cnt[i], ROW_CAP);
    float s2i = g_s2[i];
    float acc = 0.f;

    for (int base = 0; base < cnt; base += 8) {
        int j = base + u;
        int kk = -1;
        float wt = 0.f;
        if (j < cnt) {
            kk = g_row_edges[i * ROW_CAP + j];
            float2 e0 = *reinterpret_cast<const float2*>(&g_epack[kk * 16]);
            wt = __expf(leaky(e0.x + s2i)) * e0.y;
        }
        // broadcast each peer's (k, wt) within the 8-lane group; gather own dim
#pragma unroll
        for (int v = 0; v < 8; v++) {
            int kv = __shfl_sync(0xffffffffu, kk, v, 8);
            float wv = __shfl_sync(0xffffffffu, wt, v, 8);
            if (kv >= 0) acc += wv * g_epack[kv * 16 + 4 + u];
        }
    }

    const float invN = 1.f / NN;
    out[(size_t)i * DHH + u] = elu(acc + invN * g_empty_en[u]);

    // ---- restore zero-invariant for the next replay ----
    if (u == 0) g_row_cnt[i] = 0;          // own node, already consumed
    if (gid < MM) g_col_cnt[gid] = 0;      // k_enew finished (pdl_wait ordering)
    pdl_trigger();
}

// -----------------------------------------------------------------------------
extern "C" void kernel_launch(void* const* d_in, const int* in_sizes, int n_in,
                              void* d_out, int out_size) {
    const float* X  = (const float*)d_in[0];
    const float* E  = (const float*)d_in[1];
    const float* H  = (const float*)d_in[2];
    const float* W  = (const float*)d_in[3];
    const float* ax = (const float*)d_in[4];
    const float* ae = (const float*)d_in[5];
    float* out = (float*)d_out;

    cudaLaunchAttribute attr;
    attr.id = cudaLaunchAttributeProgrammaticStreamSerialization;
    attr.val.programmaticStreamSerializationAllowed = 1;

    cudaLaunchConfig_t cfg = {};
    cfg.blockDim = dim3(256);
    cfg.dynamicSmemBytes = 0;
    cfg.stream = 0;
    cfg.attrs = &attr;
    cfg.numAttrs = 1;

    cfg.gridDim = dim3(PROJ_BLOCKS + SCAN_BLOCKS);
    cudaLaunchKernelEx(&cfg, k_main, X, E, H, W, ax, ae);

    cfg.gridDim = dim3(NN * 8 / 256);
    cudaLaunchKernelEx(&cfg, k_nodestats);

    cfg.gridDim = dim3(MM * 32 / 256);
    cudaLaunchKernelEx(&cfg, k_enew);

    cfg.gridDim = dim3(NN * 8 / 256);
    cudaLaunchKernelEx(&cfg, k_xnew, out);
}

// round 6
// speedup vs baseline: 1.5701x; 1.0510x over previous
#include <cuda_runtime.h>

#define NN 8192
#define MM 2048
#define DD 256
#define DHH 8
#define ROW_CAP 64
#define COL_CAP 128
#define PROJ_BLOCKS 40          // (NN+MM)/256
#define SCAN_BLOCKS 2048
#define SCAN_ITERS 8            // NN*MM/4 / (SCAN_BLOCKS*256)

// ---------------- scratch (static device globals; zero-init at load) ---------
__device__ float g_sx[NN];
__device__ float g_s2[NN];
__device__ float g_se[MM];
__device__ float g_s1[MM];
__device__ int   g_row_cnt[NN];        // zero at entry; re-zeroed in k_out
__device__ int   g_col_cnt[MM];
__device__ __align__(16) int g_row_edges[NN * ROW_CAP];
__device__ int   g_col_nodes[MM * COL_CAP];
// packed per-node record: [sx, 1/rowSum, s2, 0, WX0..7, pad4]  (stride 16 floats)
__device__ __align__(16) float g_npack[NN * 16];
// per-edge: [0]=s1 (unused here), [1]=1/colSum
__device__ __align__(16) float g_epack[MM * 16];
__device__ __align__(16) float g_empty_wx[DHH];     // zeroed by k_main each replay
__device__ __align__(16) float g_empty_en[DHH];
__device__ float g_xacc[NN * DHH];                  // zero at entry; re-zeroed in k_out

__device__ __forceinline__ float leaky(float x) { return x >= 0.f ? x : 0.2f * x; }
__device__ __forceinline__ float elu(float x)   { return x > 0.f ? x : expm1f(x); }
__device__ __forceinline__ void pdl_wait()    { asm volatile("griddepcontrol.wait;" ::: "memory"); }
__device__ __forceinline__ void pdl_trigger() { asm volatile("griddepcontrol.launch_dependents;" ::: "memory"); }

// ---------------- K1: fused projection + H scan (independent block groups) ---
__global__ void k_main(const float* __restrict__ X, const float* __restrict__ E,
                       const float* __restrict__ H, const float* __restrict__ W,
                       const float* __restrict__ ax, const float* __restrict__ ae) {
    pdl_wait();   // previous replay's k_out restored zero-invariants
    if (blockIdx.x >= PROJ_BLOCKS) {
        int t = (blockIdx.x - PROJ_BLOCKS) * blockDim.x + threadIdx.x;
        const int stride = SCAN_BLOCKS * 256;
        const uint4* H4 = reinterpret_cast<const uint4*>(H);
        uint4 v[SCAN_ITERS];
#pragma unroll
        for (int it = 0; it < SCAN_ITERS; it++) v[it] = H4[t + it * stride];
#pragma unroll
        for (int it = 0; it < SCAN_ITERS; it++) {
            uint4 h = v[it];
            if (h.x | h.y | h.z | h.w) {
                int base = (t + it * stride) * 4;
                unsigned c4[4] = {h.x, h.y, h.z, h.w};
#pragma unroll
                for (int c = 0; c < 4; c++) {
                    if (c4[c]) {
                        int lin = base + c;
                        int i = lin >> 11;        // / MM
                        int k = lin & (MM - 1);   // % MM
                        int p = atomicAdd(&g_row_cnt[i], 1);
                        if (p < ROW_CAP) g_row_edges[i * ROW_CAP + p] = k;
                        int q = atomicAdd(&g_col_cnt[k], 1);
                        if (q < COL_CAP) g_col_nodes[k * COL_CAP + q] = i;
                    }
                }
            }
        }
        pdl_trigger();
        return;
    }

    // ---- projection: rows 0..NN-1 -> X, NN..NN+MM-1 -> E ----
    __shared__ float sW[DD * DHH];
    __shared__ float sax[2 * DHH], sae[2 * DHH];
    for (int j = threadIdx.x; j < DD * DHH; j += blockDim.x) sW[j] = W[j];
    if (threadIdx.x < 2 * DHH) {
        sax[threadIdx.x] = ax[threadIdx.x];
        sae[threadIdx.x] = ae[threadIdx.x];
    }
    __syncthreads();

    int r = blockIdx.x * blockDim.x + threadIdx.x;   // 0..10239
    if (r < DHH) { g_empty_wx[r] = 0.f; g_empty_en[r] = 0.f; }

    const float* src = (r < NN) ? (X + (size_t)r * DD)
                                : (E + (size_t)(r - NN) * DD);
    float acc[DHH];
#pragma unroll
    for (int d = 0; d < DHH; d++) acc[d] = 0.f;

    const float4* Ar = reinterpret_cast<const float4*>(src);
#pragma unroll 4
    for (int j4 = 0; j4 < DD / 4; j4++) {
        float4 x = Ar[j4];
        int j = 4 * j4;
#pragma unroll
        for (int d = 0; d < DHH; d++) acc[d] += x.x * sW[(j + 0) * DHH + d];
#pragma unroll
        for (int d = 0; d < DHH; d++) acc[d] += x.y * sW[(j + 1) * DHH + d];
#pragma unroll
        for (int d = 0; d < DHH; d++) acc[d] += x.z * sW[(j + 2) * DHH + d];
#pragma unroll
        for (int d = 0; d < DHH; d++) acc[d] += x.w * sW[(j + 3) * DHH + d];
    }

    if (r < NN) {
        float d1 = 0.f, d2 = 0.f;
#pragma unroll
        for (int d = 0; d < DHH; d++) {
            d1 += acc[d] * sax[d];          // alpha_x[:dh]
            d2 += acc[d] * sae[DHH + d];    // alpha_e[dh:]
        }
        g_sx[r] = d1; g_s2[r] = d2;
        float4* np = reinterpret_cast<float4*>(&g_npack[r * 16]);
        np[0] = make_float4(d1, 0.f, d2, 0.f);
        np[1] = make_float4(acc[0], acc[1], acc[2], acc[3]);
        np[2] = make_float4(acc[4], acc[5], acc[6], acc[7]);
    } else {
        int k = r - NN;
        float d1 = 0.f, d2 = 0.f;
#pragma unroll
        for (int d = 0; d < DHH; d++) {
            d1 += acc[d] * sax[DHH + d];    // alpha_x[dh:]
            d2 += acc[d] * sae[d];          // alpha_e[:dh]
        }
        g_se[k] = d1; g_s1[k] = d2;
    }
    pdl_trigger();
}

// ---------------- K2: row exp-sums (8 lanes/node) + col exp-sums (8/edge) ----
__global__ void k_stats() {
    pdl_wait();
    int gid = blockIdx.x * blockDim.x + threadIdx.x;   // (NN+MM)*8 threads
    if (gid < NN * 8) {
        int i = gid >> 3, l8 = gid & 7;
        int cnt = min(g_row_cnt[i], ROW_CAP);
        if (cnt == 0) {
            atomicAdd(&g_empty_wx[l8], g_npack[i * 16 + 4 + l8]);
        } else {
            float sxi = g_sx[i];
            float s = 0.f;
            for (int j = l8; j < cnt; j += 8)
                s += __expf(leaky(sxi + g_se[g_row_edges[i * ROW_CAP + j]]));
            s += __shfl_xor_sync(0xffffffffu, s, 4);
            s += __shfl_xor_sync(0xffffffffu, s, 2);
            s += __shfl_xor_sync(0xffffffffu, s, 1);
            if (l8 == 0) g_npack[i * 16 + 1] = 1.f / s;
        }
    } else {
        int g2 = gid - NN * 8;
        int k = g2 >> 3, l8 = g2 & 7;
        int cnt = min(g_col_cnt[k], COL_CAP);
        if (cnt > 0) {
            float s1k = g_s1[k];
            float s = 0.f;
            for (int j = l8; j < cnt; j += 8)
                s += __expf(leaky(s1k + g_s2[g_col_nodes[k * COL_CAP + j]]));
            s += __shfl_xor_sync(0xffffffffu, s, 4);
            s += __shfl_xor_sync(0xffffffffu, s, 2);
            s += __shfl_xor_sync(0xffffffffu, s, 1);
            if (l8 == 0) g_epack[k * 16 + 1] = 1.f / s;
        }
    }
    pdl_trigger();
}

// ---------------- K3: E_new (warp/edge) + scatter into xacc ------------------
__global__ void k_enew() {
    pdl_wait();
    int gid = blockIdx.x * blockDim.x + threadIdx.x;
    int k = gid >> 5;                                 // exactly MM warps
    int lane = gid & 31;
    int cnt = min(g_col_cnt[k], COL_CAP);
    const float invM = 1.f / MM;

    if (cnt == 0) {
        if (lane < DHH)
            atomicAdd(&g_empty_en[lane], elu(invM * g_empty_wx[lane]));
        pdl_trigger();
        return;
    }

    float sek = g_se[k], s1k = g_s1[k];
    float invColS = g_epack[k * 16 + 1];
    float acc[DHH];
#pragma unroll
    for (int d = 0; d < DHH; d++) acc[d] = 0.f;

    int   iv[COL_CAP / 32];
    float wsv[COL_CAP / 32];
    int nit = 0;
    for (int j = lane; j < cnt; j += 32) {
        int i = g_col_nodes[k * COL_CAP + j];
        const float4* np = reinterpret_cast<const float4*>(&g_npack[i * 16]);
        float4 p0 = np[0], p1 = np[1], p2 = np[2];
        float wt = __expf(leaky(p0.x + sek)) * p0.y;         // node->edge att
        acc[0] += wt * p1.x; acc[1] += wt * p1.y; acc[2] += wt * p1.z; acc[3] += wt * p1.w;
        acc[4] += wt * p2.x; acc[5] += wt * p2.y; acc[6] += wt * p2.z; acc[7] += wt * p2.w;
        iv[nit] = i;
        wsv[nit] = __expf(leaky(s1k + p0.z)) * invColS;      // edge->node att
        nit++;
    }

    // xor-butterfly: ALL lanes end with the full sums
#pragma unroll
    for (int d = 0; d < DHH; d++)
#pragma unroll
        for (int off = 16; off > 0; off >>= 1)
            acc[d] += __shfl_xor_sync(0xffffffffu, acc[d], off);

    float4 ew0 = *reinterpret_cast<const float4*>(&g_empty_wx[0]);
    float4 ew1 = *reinterpret_cast<const float4*>(&g_empty_wx[4]);
    float en[DHH];
    en[0] = elu(acc[0] + invM * ew0.x); en[1] = elu(acc[1] + invM * ew0.y);
    en[2] = elu(acc[2] + invM * ew0.z); en[3] = elu(acc[3] + invM * ew0.w);
    en[4] = elu(acc[4] + invM * ew1.x); en[5] = elu(acc[5] + invM * ew1.y);
    en[6] = elu(acc[6] + invM * ew1.z); en[7] = elu(acc[7] + invM * ew1.w);

    // scatter: xacc[i][d] += w_edge(k,i) * Enew[k][d]
    for (int t = 0; t < nit; t++) {
        float* dst = &g_xacc[iv[t] * DHH];
        float w = wsv[t];
#pragma unroll
        for (int d = 0; d < DHH; d++) atomicAdd(dst + d, w * en[d]);
    }
    pdl_trigger();
}

// ---------------- K4: epilogue: out = elu(xacc + invN*empty_en); cleanup -----
__global__ void k_out(float* __restrict__ out) {
    pdl_wait();
    int gid = blockIdx.x * blockDim.x + threadIdx.x;   // NN*8 threads
    int u = gid & 7;
    const float invN = 1.f / NN;
    out[gid] = elu(g_xacc[gid] + invN * g_empty_en[u]);
    // ---- restore zero-invariants for next replay ----
    g_xacc[gid] = 0.f;
    if (gid < NN) g_row_cnt[gid] = 0;
    if (gid < MM) g_col_cnt[gid] = 0;
    pdl_trigger();
}

// -----------------------------------------------------------------------------
extern "C" void kernel_launch(void* const* d_in, const int* in_sizes, int n_in,
                              void* d_out, int out_size) {
    const float* X  = (const float*)d_in[0];
    const float* E  = (const float*)d_in[1];
    const float* H  = (const float*)d_in[2];
    const float* W  = (const float*)d_in[3];
    const float* ax = (const float*)d_in[4];
    const float* ae = (const float*)d_in[5];
    float* out = (float*)d_out;

    cudaLaunchAttribute attr;
    attr.id = cudaLaunchAttributeProgrammaticStreamSerialization;
    attr.val.programmaticStreamSerializationAllowed = 1;

    cudaLaunchConfig_t cfg = {};
    cfg.blockDim = dim3(256);
    cfg.dynamicSmemBytes = 0;
    cfg.stream = 0;
    cfg.attrs = &attr;
    cfg.numAttrs = 1;

    cfg.gridDim = dim3(PROJ_BLOCKS + SCAN_BLOCKS);
    cudaLaunchKernelEx(&cfg, k_main, X, E, H, W, ax, ae);

    cfg.gridDim = dim3((NN + MM) * 8 / 256);
    cudaLaunchKernelEx(&cfg, k_stats);

    cfg.gridDim = dim3(MM * 32 / 256);
    cudaLaunchKernelEx(&cfg, k_enew);

    cfg.gridDim = dim3(NN * 8 / 256);
    cudaLaunchKernelEx(&cfg, k_out, out);
}